// round 14
// baseline (speedup 1.0000x reference)
#include <cuda_runtime.h>
#include <cuda_fp16.h>
#include <cstdint>

// Problem constants
#define K_NODES 100000
#define K_RELS  500
#define K_MEM   512
#define K_IN    1024
#define K_BATCH 65536

// GEMM tiling: CTA 256x128, 512 threads (16 warps, m64n32 each), fp16 BK=64
#define BM 256
#define BN 128
#define BK 64                         // halves per k-chunk (= 128 B/row)
#define STR_H 72                      // halves/row (144 B) — ldmatrix conflict-free
#define A_TILE_H (BM * STR_H)         // 18432 halves
#define B_TILE_H (BN * STR_H)         // 9216 halves
#define STAGE_H (A_TILE_H + B_TILE_H)
#define STAGE_BYTES (STAGE_H * 2)     // 55296
#define NSTAGE 3
#define SMEM_BYTES (NSTAGE * STAGE_BYTES)   // 165888
#define NIT (K_IN / BK)               // 16 k-chunks

// fp16 scratch: X [2][65536][1024] halves = 256 MB, W [2][512][1024] = 2 MB
__device__ uint32_t g_Xh[(size_t)2 * K_BATCH * K_IN / 2];
__device__ uint32_t g_Wh[(size_t)2 * K_MEM * K_IN / 2];

__device__ __forceinline__ int decode_time(const void* p) {
    int i = *(const int*)p;
    if (i < 0 || i > 1000000) i = (int)__int_as_float(i);
    return i;
}

// ---------------------------------------------------------------------------
// Kernel 0a/0b: convert X / W to fp16
// ---------------------------------------------------------------------------
__global__ void conv_x_kernel(const float* __restrict__ Xn,
                              const float* __restrict__ Xr) {
    const size_t i = (size_t)blockIdx.x * blockDim.x + threadIdx.x;  // float4 idx
    const float4 v = ((const float4*)(blockIdx.y ? Xr : Xn))[i];
    __half2 lo = __floats2half2_rn(v.x, v.y);
    __half2 hi = __floats2half2_rn(v.z, v.w);
    uint2 o;
    o.x = *(uint32_t*)&lo;
    o.y = *(uint32_t*)&hi;
    ((uint2*)(g_Xh + (size_t)blockIdx.y * K_BATCH * K_IN / 2))[i] = o;
}
__global__ void conv_w_kernel(const float* __restrict__ Wn,
                              const float* __restrict__ Wr) {
    const size_t i = (size_t)blockIdx.x * blockDim.x + threadIdx.x;
    const float4 v = ((const float4*)(blockIdx.y ? Wr : Wn))[i];
    __half2 lo = __floats2half2_rn(v.x, v.y);
    __half2 hi = __floats2half2_rn(v.z, v.w);
    uint2 o;
    o.x = *(uint32_t*)&lo;
    o.y = *(uint32_t*)&hi;
    ((uint2*)(g_Wh + (size_t)blockIdx.y * K_MEM * K_IN / 2))[i] = o;
}

// ---------------------------------------------------------------------------
// Kernel 1: out[concat(entity, rel)] = memory * (t/(t+1) if t>1 else 1)
// ---------------------------------------------------------------------------
__global__ void init_out_kernel(const float* __restrict__ ent,
                                const float* __restrict__ rel,
                                const void* __restrict__ tp,
                                float* __restrict__ out) {
    const int t = decode_time(tp);
    const float s = (t > 1) ? (float)t / (float)(t + 1) : 1.0f;
    const long nent = (long)K_NODES * K_MEM;
    const long ntot = nent + (long)K_RELS * K_MEM;
    long i = ((long)blockIdx.x * blockDim.x + threadIdx.x) * 4;
    const long stride = (long)gridDim.x * blockDim.x * 4;
    for (; i < ntot; i += stride) {
        const float4 v = (i < nent) ? *(const float4*)(ent + i)
                                    : *(const float4*)(rel + (i - nent));
        float4 o;
        o.x = v.x * s; o.y = v.y * s; o.z = v.z * s; o.w = v.w * s;
        *(float4*)(out + i) = o;
    }
}

// ---------------------------------------------------------------------------
// Kernel 2: C = X @ W^T (+bias), scaled, scatter-added. fp16 mma m16n8k16,
// fp32 accumulate. CTA 256x128 (512 thr, 16 warps m64n32), 3-stage cp.async
// ring, one barrier per chunk. grid = (MEM/BN, BATCH/BM, 2), col tiles fastest.
// ---------------------------------------------------------------------------
__device__ __forceinline__ void cp16(void* smem_dst, const void* gsrc) {
    uint32_t d = (uint32_t)__cvta_generic_to_shared(smem_dst);
    asm volatile("cp.async.cg.shared.global [%0], [%1], 16;" :: "r"(d), "l"(gsrc));
}
__device__ __forceinline__ void ldsm4(uint32_t& r0, uint32_t& r1,
                                      uint32_t& r2, uint32_t& r3, uint32_t a) {
    asm volatile("ldmatrix.sync.aligned.m8n8.x4.shared.b16 {%0,%1,%2,%3}, [%4];"
                 : "=r"(r0), "=r"(r1), "=r"(r2), "=r"(r3) : "r"(a));
}

__global__ __launch_bounds__(512, 1) void gemm_scatter_kernel(
    const float* __restrict__ bn, const float* __restrict__ br,
    const int* __restrict__ idn, const int* __restrict__ idr,
    const void* __restrict__ tp, float* __restrict__ out)
{
    extern __shared__ __half smem[];   // 3 stages of [A | B]

    const int z = blockIdx.z;
    const uint32_t* __restrict__ Xh  = g_Xh + (size_t)z * K_BATCH * K_IN / 2;
    const uint32_t* __restrict__ Wh  = g_Wh + (size_t)z * K_MEM * K_IN / 2;
    const float*    __restrict__ bias = z ? br : bn;
    const int*      __restrict__ ids  = z ? idr : idn;
    const int obase = z ? K_NODES : 0;

    const int t = decode_time(tp);
    const float inv = 1.0f / (float)(t + 1);

    const int bm    = blockIdx.y * BM;
    const int bnoff = blockIdx.x * BN;
    const int tid  = threadIdx.x;
    const int wid  = tid >> 5, lane = tid & 31;
    const int wm = (wid & 3) * 64;        // 4 warp rows  (m256)
    const int wn = (wid >> 2) * 32;       // 4 warp cols  (n128)
    const int grp = lane >> 2, tig = lane & 3;

    // ldmatrix per-lane offsets (bytes) — mapping validated in R6/R13
    const uint32_t aoff =
        ((((lane & 7) + ((lane >> 3) & 1) * 8) * STR_H) + ((lane >> 4) & 1) * 8) * 2;
    const uint32_t boff =
        ((((lane & 7) + ((lane >> 4) & 1) * 8) * STR_H) + ((lane >> 3) & 1) * 8) * 2;

    const uint32_t smem0 = (uint32_t)__cvta_generic_to_shared(smem);
    const uint32_t aBase0 = smem0 + (uint32_t)(wm * STR_H * 2) + aoff;
    const uint32_t bBase0 = smem0 + (uint32_t)(A_TILE_H * 2)
                          + (uint32_t)(wn * STR_H * 2) + boff;

    // Incremental fill pointers: thread covers row tid>>3 (+i*64), 16B chunk tid&7
    const char* gA = (const char*)Xh + ((size_t)(bm    + (tid >> 3)) * K_IN
                                        + ((tid & 7) << 3)) * 2;
    const char* gB = (const char*)Wh + ((size_t)(bnoff + (tid >> 3)) * K_IN
                                        + ((tid & 7) << 3)) * 2;
    const int sdst = (tid >> 3) * STR_H + ((tid & 7) << 3);   // halves

    auto fill = [&](int st) {
        __half* dA = smem + st * STAGE_H + sdst;
        __half* dB = dA + A_TILE_H;
        #pragma unroll
        for (int i = 0; i < 4; i++)                       // A: 256 rows
            cp16(dA + i * 64 * STR_H, gA + (size_t)i * 64 * K_IN * 2);
        #pragma unroll
        for (int i = 0; i < 2; i++)                       // B: 128 rows
            cp16(dB + i * 64 * STR_H, gB + (size_t)i * 64 * K_IN * 2);
        asm volatile("cp.async.commit_group;");
        gA += BK * 2;
        gB += BK * 2;
    };

    float acc[4][4][4] = {};   // 64 accumulators (m64 x n32)

    fill(0); fill(1);

    for (int it = 0; it < NIT; ++it) {
        const int st = it % 3;
        asm volatile("cp.async.wait_group 1;");
        __syncthreads();                       // single barrier per chunk

        // Refill stage 2 ahead (ring: never the stage being read now or next)
        if (it + 2 < NIT) fill((it + 2) % 3);
        else asm volatile("cp.async.commit_group;");

        const uint32_t aB = aBase0 + st * STAGE_BYTES;
        const uint32_t bB = bBase0 + st * STAGE_BYTES;

        #pragma unroll
        for (int ks = 0; ks < 4; ++ks) {       // 4 x k16 per chunk
            uint32_t af[4][4], bf[4][2];
            #pragma unroll
            for (int mt = 0; mt < 4; ++mt) {
                ldsm4(af[mt][0], af[mt][1], af[mt][2], af[mt][3],
                      aB + mt * (16 * STR_H * 2) + ks * 32);
            }
            #pragma unroll
            for (int np = 0; np < 2; ++np) {
                uint32_t r0, r1, r2, r3;
                ldsm4(r0, r1, r2, r3, bB + np * (16 * STR_H * 2) + ks * 32);
                bf[2 * np][0]     = r0;
                bf[2 * np][1]     = r1;
                bf[2 * np + 1][0] = r2;
                bf[2 * np + 1][1] = r3;
            }
            #pragma unroll
            for (int mt = 0; mt < 4; ++mt)
                #pragma unroll
                for (int nt = 0; nt < 4; ++nt)
                    asm volatile(
                        "mma.sync.aligned.m16n8k16.row.col.f32.f16.f16.f32 "
                        "{%0,%1,%2,%3}, {%4,%5,%6,%7}, {%8,%9}, {%0,%1,%2,%3};"
                        : "+f"(acc[mt][nt][0]), "+f"(acc[mt][nt][1]),
                          "+f"(acc[mt][nt][2]), "+f"(acc[mt][nt][3])
                        : "r"(af[mt][0]), "r"(af[mt][1]), "r"(af[mt][2]), "r"(af[mt][3]),
                          "r"(bf[nt][0]), "r"(bf[nt][1]));
        }
    }

    // Epilogue: (acc + bias) * inv, scatter-add via float2 vector atomics
    float2 bv[4];
    #pragma unroll
    for (int nt = 0; nt < 4; ++nt) {
        int col = bnoff + wn + nt * 8 + tig * 2;
        bv[nt].x = bias[col];
        bv[nt].y = bias[col + 1];
    }
    #pragma unroll
    for (int mt = 0; mt < 4; ++mt) {
        #pragma unroll
        for (int h = 0; h < 2; ++h) {
            const int gb = bm + wm + mt * 16 + grp + h * 8;
            const long orow = (long)(ids[gb] + obase);
            float* dst = out + orow * K_MEM;
            #pragma unroll
            for (int nt = 0; nt < 4; ++nt) {
                const int col = bnoff + wn + nt * 8 + tig * 2;
                float2 v;
                v.x = (acc[mt][nt][h * 2 + 0] + bv[nt].x) * inv;
                v.y = (acc[mt][nt][h * 2 + 1] + bv[nt].y) * inv;
                atomicAdd((float2*)(dst + col), v);
            }
        }
    }
}

// ---------------------------------------------------------------------------
extern "C" void kernel_launch(void* const* d_in, const int* in_sizes, int n_in,
                              void* d_out, int out_size) {
    const float* Xn  = (const float*)d_in[0];
    const float* Xr  = (const float*)d_in[1];
    const int*   idn = (const int*)  d_in[2];
    const int*   idr = (const int*)  d_in[3];
    const float* ent = (const float*)d_in[4];
    const float* rel = (const float*)d_in[5];
    const float* Wn  = (const float*)d_in[6];
    const float* bn  = (const float*)d_in[7];
    const float* Wr  = (const float*)d_in[8];
    const float* br  = (const float*)d_in[9];
    const void*  tp  = d_in[10];
    float* out = (float*)d_out;

    // 0) X, W -> fp16 scratch
    conv_x_kernel<<<dim3(K_BATCH * (K_IN / 4) / 256, 2), 256>>>(Xn, Xr);
    conv_w_kernel<<<dim3(K_MEM * (K_IN / 4) / 256, 2), 256>>>(Wn, Wr);

    // 1) out = scaled memory state
    init_out_kernel<<<1184, 256>>>(ent, rel, tp, out);

    // 2) GEMM + scatter-add
    cudaFuncSetAttribute(gemm_scatter_kernel,
                         cudaFuncAttributeMaxDynamicSharedMemorySize, SMEM_BYTES);
    dim3 grid(K_MEM / BN, K_BATCH / BM, 2);
    gemm_scatter_kernel<<<grid, 512, SMEM_BYTES>>>(
        bn, br, idn, idr, tp, out);
}

// round 15
// speedup vs baseline: 1.1384x; 1.1384x over previous
#include <cuda_runtime.h>
#include <cuda_fp16.h>
#include <cstdint>

// Problem constants
#define K_NODES 100000
#define K_RELS  500
#define K_MEM   512
#define K_IN    1024
#define K_BATCH 65536

// GEMM tiling (R13 shape: CTA 128x128, 256 thr, 2 CTA/SM, fp16 BK=64)
#define BM 128
#define BN 128
#define BK 64                         // halves (or floats) per k-chunk
#define STR_H 72                      // halves/row (144 B) — ldmatrix conflict-free
#define A_TILE_H (BM * STR_H)         // 9216 halves
#define B_TILE_H (BN * STR_H)         // 9216 halves
#define STAGE_H (A_TILE_H + B_TILE_H)
#define STAGE_BYTES (STAGE_H * 2)     // 36864
#define NSTAGE 3
#define SMEM_BYTES (NSTAGE * STAGE_BYTES)   // 110592
#define NIT (K_IN / BK)               // 16 k-chunks

// fp16 scratch for W only: [2][512][1024] halves = 2 MB
__device__ uint32_t g_Wh[(size_t)2 * K_MEM * K_IN / 2];

__device__ __forceinline__ int decode_time(const void* p) {
    int i = *(const int*)p;
    if (i < 0 || i > 1000000) i = (int)__int_as_float(i);
    return i;
}

// ---------------------------------------------------------------------------
// Kernel 0: convert W to fp16
// ---------------------------------------------------------------------------
__global__ void conv_w_kernel(const float* __restrict__ Wn,
                              const float* __restrict__ Wr) {
    const size_t i = (size_t)blockIdx.x * blockDim.x + threadIdx.x;
    const float4 v = ((const float4*)(blockIdx.y ? Wr : Wn))[i];
    __half2 lo = __floats2half2_rn(v.x, v.y);
    __half2 hi = __floats2half2_rn(v.z, v.w);
    uint2 o;
    o.x = *(uint32_t*)&lo;
    o.y = *(uint32_t*)&hi;
    ((uint2*)(g_Wh + (size_t)blockIdx.y * K_MEM * K_IN / 2))[i] = o;
}

// ---------------------------------------------------------------------------
// Kernel 1: out[concat(entity, rel)] = memory * (t/(t+1) if t>1 else 1)
// ---------------------------------------------------------------------------
__global__ void init_out_kernel(const float* __restrict__ ent,
                                const float* __restrict__ rel,
                                const void* __restrict__ tp,
                                float* __restrict__ out) {
    const int t = decode_time(tp);
    const float s = (t > 1) ? (float)t / (float)(t + 1) : 1.0f;
    const long nent = (long)K_NODES * K_MEM;
    const long ntot = nent + (long)K_RELS * K_MEM;
    long i = ((long)blockIdx.x * blockDim.x + threadIdx.x) * 4;
    const long stride = (long)gridDim.x * blockDim.x * 4;
    for (; i < ntot; i += stride) {
        const float4 v = (i < nent) ? *(const float4*)(ent + i)
                                    : *(const float4*)(rel + (i - nent));
        float4 o;
        o.x = v.x * s; o.y = v.y * s; o.z = v.z * s; o.w = v.w * s;
        *(float4*)(out + i) = o;
    }
}

// ---------------------------------------------------------------------------
// Kernel 2: C = X @ W^T (+bias), scaled, scatter-added. fp16 mma m16n8k16.
// A-side: fp32 X loaded by LDG, converted to fp16 in registers, STS into the
// smem stage (conversion fused into the GEMM — no separate conv_x pass).
// B-side: cp.async from pre-converted g_Wh. Mainloop identical to R13.
// grid = (MEM/BN, BATCH/BM, 2), col tiles fastest (L2 A-reuse).
// ---------------------------------------------------------------------------
__device__ __forceinline__ void cp16(void* smem_dst, const void* gsrc) {
    uint32_t d = (uint32_t)__cvta_generic_to_shared(smem_dst);
    asm volatile("cp.async.cg.shared.global [%0], [%1], 16;" :: "r"(d), "l"(gsrc));
}
__device__ __forceinline__ void ldsm4(uint32_t& r0, uint32_t& r1,
                                      uint32_t& r2, uint32_t& r3, uint32_t a) {
    asm volatile("ldmatrix.sync.aligned.m8n8.x4.shared.b16 {%0,%1,%2,%3}, [%4];"
                 : "=r"(r0), "=r"(r1), "=r"(r2), "=r"(r3) : "r"(a));
}

__global__ __launch_bounds__(256, 2) void gemm_scatter_kernel(
    const float* __restrict__ Xn, const float* __restrict__ Xr,
    const float* __restrict__ bn, const float* __restrict__ br,
    const int* __restrict__ idn, const int* __restrict__ idr,
    const void* __restrict__ tp, float* __restrict__ out)
{
    extern __shared__ __half smem[];   // 3 stages of [A | B]

    const int z = blockIdx.z;
    const float*    __restrict__ Xf  = z ? Xr : Xn;
    const uint32_t* __restrict__ Wh  = g_Wh + (size_t)z * K_MEM * K_IN / 2;
    const float*    __restrict__ bias = z ? br : bn;
    const int*      __restrict__ ids  = z ? idr : idn;
    const int obase = z ? K_NODES : 0;

    const int t = decode_time(tp);
    const float inv = 1.0f / (float)(t + 1);

    const int bm    = blockIdx.y * BM;
    const int bnoff = blockIdx.x * BN;
    const int tid  = threadIdx.x;
    const int wid  = tid >> 5, lane = tid & 31;
    const int wm = (wid & 1) * 64;
    const int wn = (wid >> 1) * 32;
    const int grp = lane >> 2, tig = lane & 3;

    // ldmatrix per-lane offsets (bytes) — mapping validated in R6/R13
    const uint32_t aoff =
        ((((lane & 7) + ((lane >> 3) & 1) * 8) * STR_H) + ((lane >> 4) & 1) * 8) * 2;
    const uint32_t boff =
        ((((lane & 7) + ((lane >> 4) & 1) * 8) * STR_H) + ((lane >> 3) & 1) * 8) * 2;

    const uint32_t smem0 = (uint32_t)__cvta_generic_to_shared(smem);
    const uint32_t aBase0 = smem0 + (uint32_t)(wm * STR_H * 2) + aoff;
    const uint32_t bBase0 = smem0 + (uint32_t)(A_TILE_H * 2)
                          + (uint32_t)(wn * STR_H * 2) + boff;

    // --- Fill-side indexing ---
    const int r0  = tid >> 3;             // 0..31 (row within 32-row group)
    const int c8  = (tid & 7) * 8;        // 8-element column offset
    // A: fp32 global, 8 floats (2 float4) per thread per 32-row group, 4 groups
    const float* gA = Xf + (size_t)(bm + r0) * K_IN + c8;
    // B: fp16 global (g_Wh), cp.async 16B per thread per group, 4 groups
    const char* gB = (const char*)Wh + ((size_t)(bnoff + r0) * K_IN + c8) * 2;
    const int sdstB = r0 * STR_H + c8;    // halves

    float4 v[2][2];                       // A staging (2 groups in flight)

    auto ldgA2 = [&](int p) {
        #pragma unroll
        for (int j = 0; j < 2; ++j) {
            const float* s = gA + (size_t)(2 * p + j) * 32 * K_IN;
            v[j][0] = __ldg((const float4*)s);
            v[j][1] = __ldg((const float4*)(s + 4));
        }
    };
    auto stsA2 = [&](int p, int st) {
        #pragma unroll
        for (int j = 0; j < 2; ++j) {
            __half2 h0 = __floats2half2_rn(v[j][0].x, v[j][0].y);
            __half2 h1 = __floats2half2_rn(v[j][0].z, v[j][0].w);
            __half2 h2 = __floats2half2_rn(v[j][1].x, v[j][1].y);
            __half2 h3 = __floats2half2_rn(v[j][1].z, v[j][1].w);
            uint4 u;
            u.x = *(uint32_t*)&h0; u.y = *(uint32_t*)&h1;
            u.z = *(uint32_t*)&h2; u.w = *(uint32_t*)&h3;
            *(uint4*)(smem + st * STAGE_H
                      + (r0 + (2 * p + j) * 32) * STR_H + c8) = u;
        }
    };
    auto fillB = [&](int st) {
        __half* dB = smem + st * STAGE_H + A_TILE_H + sdstB;
        #pragma unroll
        for (int i = 0; i < 4; i++)
            cp16(dB + i * 32 * STR_H, gB + (size_t)i * 32 * K_IN * 2);
        asm volatile("cp.async.commit_group;");
        gB += BK * 2;
    };

    float acc[4][4][4] = {};   // 64 accumulators (m64 x n32)

    // Prologue: A chunks 0,1 via LDG->CVT->STS; B chunks 0,1 via cp.async
    ldgA2(0); stsA2(0, 0); ldgA2(1); stsA2(1, 0); gA += BK;
    ldgA2(0); stsA2(0, 1); ldgA2(1); stsA2(1, 1); gA += BK;
    fillB(0); fillB(1);

    auto doks = [&](uint32_t aB, uint32_t bB, int ks) {
        uint32_t af[4][4], bf[4][2];
        #pragma unroll
        for (int mt = 0; mt < 4; ++mt)
            ldsm4(af[mt][0], af[mt][1], af[mt][2], af[mt][3],
                  aB + mt * (16 * STR_H * 2) + ks * 32);
        #pragma unroll
        for (int np = 0; np < 2; ++np) {
            uint32_t q0, q1, q2, q3;
            ldsm4(q0, q1, q2, q3, bB + np * (16 * STR_H * 2) + ks * 32);
            bf[2 * np][0] = q0; bf[2 * np][1] = q1;
            bf[2 * np + 1][0] = q2; bf[2 * np + 1][1] = q3;
        }
        #pragma unroll
        for (int mt = 0; mt < 4; ++mt)
            #pragma unroll
            for (int nt = 0; nt < 4; ++nt)
                asm volatile(
                    "mma.sync.aligned.m16n8k16.row.col.f32.f16.f16.f32 "
                    "{%0,%1,%2,%3}, {%4,%5,%6,%7}, {%8,%9}, {%0,%1,%2,%3};"
                    : "+f"(acc[mt][nt][0]), "+f"(acc[mt][nt][1]),
                      "+f"(acc[mt][nt][2]), "+f"(acc[mt][nt][3])
                    : "r"(af[mt][0]), "r"(af[mt][1]), "r"(af[mt][2]), "r"(af[mt][3]),
                      "r"(bf[nt][0]), "r"(bf[nt][1]));
    };

    for (int it = 0; it < NIT; ++it) {
        const int st = it % 3;
        asm volatile("cp.async.wait_group 1;");
        __syncthreads();                       // single barrier per chunk

        const int pst = (it + 2) % 3;
        const bool pf = (it + 2) < NIT;
        if (pf) fillB(pst);
        else asm volatile("cp.async.commit_group;");

        const uint32_t aB = aBase0 + st * STAGE_BYTES;
        const uint32_t bB = bBase0 + st * STAGE_BYTES;

        if (pf) ldgA2(0);                      // LDG chunk it+2, groups 0-1
        doks(aB, bB, 0);
        doks(aB, bB, 1);
        if (pf) { stsA2(0, pst); ldgA2(1); gA += BK; }   // STS 0-1, LDG 2-3
        doks(aB, bB, 2);
        doks(aB, bB, 3);
        if (pf) stsA2(1, pst);                 // STS groups 2-3
    }

    // Epilogue: (acc + bias) * inv, scatter-add via float2 vector atomics
    float2 bv[4];
    #pragma unroll
    for (int nt = 0; nt < 4; ++nt) {
        int col = bnoff + wn + nt * 8 + tig * 2;
        bv[nt].x = bias[col];
        bv[nt].y = bias[col + 1];
    }
    #pragma unroll
    for (int mt = 0; mt < 4; ++mt) {
        #pragma unroll
        for (int h = 0; h < 2; ++h) {
            const int gb = bm + wm + mt * 16 + grp + h * 8;
            const long orow = (long)(ids[gb] + obase);
            float* dst = out + orow * K_MEM;
            #pragma unroll
            for (int nt = 0; nt < 4; ++nt) {
                const int col = bnoff + wn + nt * 8 + tig * 2;
                float2 w;
                w.x = (acc[mt][nt][h * 2 + 0] + bv[nt].x) * inv;
                w.y = (acc[mt][nt][h * 2 + 1] + bv[nt].y) * inv;
                atomicAdd((float2*)(dst + col), w);
            }
        }
    }
}

// ---------------------------------------------------------------------------
extern "C" void kernel_launch(void* const* d_in, const int* in_sizes, int n_in,
                              void* d_out, int out_size) {
    const float* Xn  = (const float*)d_in[0];
    const float* Xr  = (const float*)d_in[1];
    const int*   idn = (const int*)  d_in[2];
    const int*   idr = (const int*)  d_in[3];
    const float* ent = (const float*)d_in[4];
    const float* rel = (const float*)d_in[5];
    const float* Wn  = (const float*)d_in[6];
    const float* bn  = (const float*)d_in[7];
    const float* Wr  = (const float*)d_in[8];
    const float* br  = (const float*)d_in[9];
    const void*  tp  = d_in[10];
    float* out = (float*)d_out;

    // 0) W -> fp16 scratch (X conversion is fused into the GEMM fill)
    conv_w_kernel<<<dim3(K_MEM * (K_IN / 4) / 256, 2), 256>>>(Wn, Wr);

    // 1) out = scaled memory state
    init_out_kernel<<<1184, 256>>>(ent, rel, tp, out);

    // 2) GEMM + scatter-add
    cudaFuncSetAttribute(gemm_scatter_kernel,
                         cudaFuncAttributeMaxDynamicSharedMemorySize, SMEM_BYTES);
    dim3 grid(K_MEM / BN, K_BATCH / BM, 2);
    gemm_scatter_kernel<<<grid, 256, SMEM_BYTES>>>(
        Xn, Xr, bn, br, idn, idr, tp, out);
}